// round 11
// baseline (speedup 1.0000x reference)
#include <cuda_runtime.h>

// TensorNeRF compositing: globally-compacted two-phase, self-cleaning.
//  K1 (thread-per-ray): slab test; misses write outputs; hits append
//      (ray params + window) to a global queue -> phaseB needs ONE load round.
//  K2 (warp-per-hit-ray, grid-stride): 128-sample chunks, lane owns 4
//      contiguous samples (float4 loads), one warp scan per chunk.
// Out-of-bbox samples have cumprod factor (1-0+1e-10)==1.0f exactly in f32,
// so restricting to the conservative window is exact; visited samples use the
// exact per-sample predicate.

#define S_SAMPLES 512
#define MAX_RAYS 32768
#define PHASEB_BLOCKS 592

__device__ int g_cnt  = 0;
__device__ int g_done = 0;
__device__ float4 g_qo[MAX_RAYS];   // ox, oy, oz, bitcast(ray)
__device__ float4 g_qd[MAX_RAYS];   // dx, dy, dz, bitcast(c0 | c1<<16)

__global__ __launch_bounds__(128) void phaseA_kernel(
    const float* __restrict__ rays_o,
    const float* __restrict__ rays_d,
    const float* __restrict__ aabb,
    float* __restrict__ out,
    int N)
{
    const int ray = blockIdx.x * blockDim.x + threadIdx.x;
    if (ray >= N) return;

    const float ax0 = aabb[0], ay0 = aabb[1], az0 = aabb[2];
    const float ax1 = aabb[3], ay1 = aabb[4], az1 = aabb[5];
    const float NEAR = 2.0f, FAR = 6.0f;
    const float step = 4.0f / 511.0f;

    const float ox = rays_o[ray * 3 + 0];
    const float oy = rays_o[ray * 3 + 1];
    const float oz = rays_o[ray * 3 + 2];
    const float dx = rays_d[ray * 3 + 0];
    const float dy = rays_d[ray * 3 + 1];
    const float dz = rays_d[ray * 3 + 2];

    const float idx_ = __frcp_rn(dx);
    const float idy_ = __frcp_rn(dy);
    const float idz_ = __frcp_rn(dz);
    const float txa = (ax0 - ox) * idx_, txb = (ax1 - ox) * idx_;
    const float tya = (ay0 - oy) * idy_, tyb = (ay1 - oy) * idy_;
    const float tza = (az0 - oz) * idz_, tzb = (az1 - oz) * idz_;
    float t_ent = fmaxf(fmaxf(fminf(txa, txb), fminf(tya, tyb)), fminf(tza, tzb));
    float t_exi = fminf(fminf(fmaxf(txa, txb), fmaxf(tya, tyb)), fmaxf(tza, tzb));
    t_ent = fmaxf(t_ent, NEAR);
    t_exi = fminf(t_exi, FAR);

    bool miss = (t_ent > t_exi + 2.0f * step);
    int c0 = 0, c1 = -1;
    if (!miss) {
        int s_lo = __float2int_rd((t_ent - NEAR) * (511.0f / 4.0f)) - 2;
        int s_hi = __float2int_ru((t_exi - NEAR) * (511.0f / 4.0f)) + 2;
        s_lo = max(s_lo, 0);
        s_hi = min(s_hi, S_SAMPLES - 1);
        if (s_lo > s_hi) miss = true;
        else { c0 = s_lo >> 7; c1 = s_hi >> 7; }   // 128-sample chunks
    }

    if (miss) {
        out[ray * 3 + 0] = 0.0f;
        out[ray * 3 + 1] = 0.0f;
        out[ray * 3 + 2] = 0.0f;
        out[3 * N + ray] = 0.0f;
        out[4 * N + ray] = 1.0f;
    } else {
        const int h = atomicAdd(&g_cnt, 1);
        g_qo[h] = make_float4(ox, oy, oz, __int_as_float(ray));
        g_qd[h] = make_float4(dx, dy, dz, __int_as_float(c0 | (c1 << 16)));
    }
}

__global__ __launch_bounds__(256) void phaseB_kernel(
    const float* __restrict__ sigma_feat,
    const float* __restrict__ rgb,
    const float* __restrict__ aabb,
    float* __restrict__ out,
    int N)
{
    const int lane  = threadIdx.x & 31;
    const int gwarp = (blockIdx.x * blockDim.x + threadIdx.x) >> 5;
    const int nwarp = (gridDim.x * blockDim.x) >> 5;
    const int nh = g_cnt;

    const float ax0 = aabb[0], ay0 = aabb[1], az0 = aabb[2];
    const float ax1 = aabb[3], ay1 = aabb[4], az1 = aabb[5];
    const float NEAR = 2.0f;
    const float DENSITY_SHIFT = -10.0f;
    const float step = 4.0f / 511.0f;
    const float dist = step * 25.0f;

    for (int h = gwarp; h < nh; h += nwarp) {
        const float4 qo = g_qo[h];
        const float4 qd = g_qd[h];
        const int r   = __float_as_int(qo.w);
        const int win = __float_as_int(qd.w);
        const int c0  = win & 0xffff;
        const int c1  = win >> 16;
        const float ox = qo.x, oy = qo.y, oz = qo.z;
        const float dx = qd.x, dy = qd.y, dz = qd.z;

        const float4* __restrict__ sf4 = (const float4*)(sigma_feat + (size_t)r * S_SAMPLES);
        const float4* __restrict__ rg4 = (const float4*)(rgb + (size_t)r * S_SAMPLES * 3);

        float runT = 1.0f;
        float racc = 0.0f, gacc = 0.0f, bacc = 0.0f, dacc = 0.0f;

        #pragma unroll 1
        for (int c = c0; c <= c1; ++c) {
            const float4 sv = sf4[c * 32 + lane];
            const int s0 = c * 128 + lane * 4;
            const float t0 = fmaf(step, (float)s0, NEAR);
            const float t1 = t0 + step;
            const float t2 = t1 + step;
            const float t3 = t2 + step;

            float f[4], alpha[4];
            const float feats[4] = {sv.x, sv.y, sv.z, sv.w};
            const float ts[4]    = {t0, t1, t2, t3};
            #pragma unroll
            for (int i = 0; i < 4; ++i) {
                const float t = ts[i];
                const float px = fmaf(dx, t, ox);
                const float py = fmaf(dy, t, oy);
                const float pz = fmaf(dz, t, oz);
                const bool inb = (px >= ax0) & (px <= ax1) &
                                 (py >= ay0) & (py <= ay1) &
                                 (pz >= az0) & (pz <= az1);
                const float x = feats[i] + DENSITY_SHIFT;
                float sp = (x > 20.0f) ? x : __logf(1.0f + __expf(x));
                const float sigma = inb ? sp : 0.0f;
                const float e = __expf(-sigma * dist);
                alpha[i] = 1.0f - e;
                f[i] = e + 1e-10f;
            }

            const float E1 = f[0];
            const float E2 = E1 * f[1];
            const float E3 = E2 * f[2];
            const float P  = E3 * f[3];

            float incl = P;
            #pragma unroll
            for (int off = 1; off < 32; off <<= 1) {
                const float v = __shfl_up_sync(0xffffffffu, incl, off);
                if (lane >= off) incl *= v;
            }
            float excl = __shfl_up_sync(0xffffffffu, incl, 1);
            if (lane == 0) excl = 1.0f;

            const float Tl = runT * excl;
            const float w0 = alpha[0] * Tl;
            const float w1 = alpha[1] * Tl * E1;
            const float w2 = alpha[2] * Tl * E2;
            const float w3 = alpha[3] * Tl * E3;

            const int rbase = c * 96 + lane * 3;
            const float4 r0 = rg4[rbase + 0];
            const float4 r1 = rg4[rbase + 1];
            const float4 r2 = rg4[rbase + 2];

            racc += w0 * r0.x + w1 * r0.w + w2 * r1.z + w3 * r2.y;
            gacc += w0 * r0.y + w1 * r1.x + w2 * r1.w + w3 * r2.z;
            bacc += w0 * r0.z + w1 * r1.y + w2 * r2.x + w3 * r2.w;
            dacc += w0 * t0 + w1 * t1 + w2 * t2 + w3 * t3;

            runT *= __shfl_sync(0xffffffffu, incl, 31);
        }

        #pragma unroll
        for (int off = 16; off; off >>= 1) {
            racc += __shfl_down_sync(0xffffffffu, racc, off);
            gacc += __shfl_down_sync(0xffffffffu, gacc, off);
            bacc += __shfl_down_sync(0xffffffffu, bacc, off);
            dacc += __shfl_down_sync(0xffffffffu, dacc, off);
        }

        if (lane == 0) {
            out[r * 3 + 0] = racc;
            out[r * 3 + 1] = gacc;
            out[r * 3 + 2] = bacc;
            out[3 * N + r] = dacc;
            out[4 * N + r] = runT;
        }
    }

    // Self-clean: last block resets counters for the next replay.
    __syncthreads();
    if (threadIdx.x == 0) {
        __threadfence();
        const int done = atomicAdd(&g_done, 1);
        if (done == gridDim.x - 1) {
            g_cnt  = 0;
            g_done = 0;
            __threadfence();
        }
    }
}

extern "C" void kernel_launch(void* const* d_in, const int* in_sizes, int n_in,
                              void* d_out, int out_size) {
    const float* rays_o     = (const float*)d_in[0];
    const float* rays_d     = (const float*)d_in[1];
    const float* sigma_feat = (const float*)d_in[2];
    const float* rgb        = (const float*)d_in[3];
    const float* aabb       = (const float*)d_in[4];
    float* out = (float*)d_out;

    const int N = in_sizes[0] / 3;

    phaseA_kernel<<<(N + 127) / 128, 128>>>(rays_o, rays_d, aabb, out, N);
    phaseB_kernel<<<PHASEB_BLOCKS, 256>>>(sigma_feat, rgb, aabb, out, N);
}

// round 12
// speedup vs baseline: 1.3075x; 1.3075x over previous
#include <cuda_runtime.h>

// TensorNeRF compositing: globally-compacted two-phase, self-cleaning.
//  K1 (thread-per-ray): slab test; misses write outputs; hits append packed
//      (ray params + window) to a global queue -> phaseB needs ONE load round.
//  K2 (warp-per-hit-ray, grid-stride, 592 blocks): 32-sample chunks (tight
//      windows, minimal sigma/rgb traffic), exact per-sample predicate,
//      warp-scan cumprod. Last block resets counters for the next replay.
// Out-of-bbox samples have cumprod factor (1-0+1e-10)==1.0f exactly in f32,
// so restricting to the conservative window is exact.
// R11 lesson: 128-sample chunk granularity ~3x'd DRAM traffic and lost 3.7us
// wall despite a shorter in-kernel chain; keep windows at 32-sample grain.

#define S_SAMPLES 512
#define MAX_RAYS 32768
#define PHASEB_BLOCKS 592

__device__ int g_cnt  = 0;
__device__ int g_done = 0;
__device__ float4 g_qo[MAX_RAYS];   // ox, oy, oz, bitcast(ray)
__device__ float4 g_qd[MAX_RAYS];   // dx, dy, dz, bitcast(c0 | c1<<16)

__global__ __launch_bounds__(128) void phaseA_kernel(
    const float* __restrict__ rays_o,
    const float* __restrict__ rays_d,
    const float* __restrict__ aabb,
    float* __restrict__ out,
    int N)
{
    const int ray = blockIdx.x * blockDim.x + threadIdx.x;
    if (ray >= N) return;

    const float ax0 = aabb[0], ay0 = aabb[1], az0 = aabb[2];
    const float ax1 = aabb[3], ay1 = aabb[4], az1 = aabb[5];
    const float NEAR = 2.0f, FAR = 6.0f;
    const float step = 4.0f / 511.0f;

    const float ox = rays_o[ray * 3 + 0];
    const float oy = rays_o[ray * 3 + 1];
    const float oz = rays_o[ray * 3 + 2];
    const float dx = rays_d[ray * 3 + 0];
    const float dy = rays_d[ray * 3 + 1];
    const float dz = rays_d[ray * 3 + 2];

    const float idx_ = __frcp_rn(dx);
    const float idy_ = __frcp_rn(dy);
    const float idz_ = __frcp_rn(dz);
    const float txa = (ax0 - ox) * idx_, txb = (ax1 - ox) * idx_;
    const float tya = (ay0 - oy) * idy_, tyb = (ay1 - oy) * idy_;
    const float tza = (az0 - oz) * idz_, tzb = (az1 - oz) * idz_;
    float t_ent = fmaxf(fmaxf(fminf(txa, txb), fminf(tya, tyb)), fminf(tza, tzb));
    float t_exi = fminf(fminf(fmaxf(txa, txb), fmaxf(tya, tyb)), fmaxf(tza, tzb));
    t_ent = fmaxf(t_ent, NEAR);
    t_exi = fminf(t_exi, FAR);

    bool miss = (t_ent > t_exi + 2.0f * step);
    int c0 = 0, c1 = -1;
    if (!miss) {
        int s_lo = __float2int_rd((t_ent - NEAR) * (511.0f / 4.0f)) - 2;
        int s_hi = __float2int_ru((t_exi - NEAR) * (511.0f / 4.0f)) + 2;
        s_lo = max(s_lo, 0);
        s_hi = min(s_hi, S_SAMPLES - 1);
        if (s_lo > s_hi) miss = true;
        else { c0 = s_lo >> 5; c1 = s_hi >> 5; }   // 32-sample chunks
    }

    if (miss) {
        out[ray * 3 + 0] = 0.0f;
        out[ray * 3 + 1] = 0.0f;
        out[ray * 3 + 2] = 0.0f;
        out[3 * N + ray] = 0.0f;
        out[4 * N + ray] = 1.0f;
    } else {
        const int h = atomicAdd(&g_cnt, 1);
        g_qo[h] = make_float4(ox, oy, oz, __int_as_float(ray));
        g_qd[h] = make_float4(dx, dy, dz, __int_as_float(c0 | (c1 << 16)));
    }
}

__global__ __launch_bounds__(256) void phaseB_kernel(
    const float* __restrict__ sigma_feat,
    const float* __restrict__ rgb,
    const float* __restrict__ aabb,
    float* __restrict__ out,
    int N)
{
    const int lane  = threadIdx.x & 31;
    const int gwarp = (blockIdx.x * blockDim.x + threadIdx.x) >> 5;
    const int nwarp = (gridDim.x * blockDim.x) >> 5;
    const int nh = g_cnt;

    const float ax0 = aabb[0], ay0 = aabb[1], az0 = aabb[2];
    const float ax1 = aabb[3], ay1 = aabb[4], az1 = aabb[5];
    const float NEAR = 2.0f;
    const float DENSITY_SHIFT = -10.0f;
    const float step = 4.0f / 511.0f;
    const float dist = step * 25.0f;

    for (int h = gwarp; h < nh; h += nwarp) {
        const float4 qo = g_qo[h];
        const float4 qd = g_qd[h];
        const int r   = __float_as_int(qo.w);
        const int win = __float_as_int(qd.w);
        const int c0  = win & 0xffff;
        const int c1  = win >> 16;
        const float ox = qo.x, oy = qo.y, oz = qo.z;
        const float dx = qd.x, dy = qd.y, dz = qd.z;

        const float* __restrict__ sf = sigma_feat + (size_t)r * S_SAMPLES;
        const float* __restrict__ rg = rgb + (size_t)r * S_SAMPLES * 3;

        float runT = 1.0f;
        float racc = 0.0f, gacc = 0.0f, bacc = 0.0f, dacc = 0.0f;

        #pragma unroll 1
        for (int c = c0; c <= c1; ++c) {
            const int s = c * 32 + lane;
            const float t = fmaf(step, (float)s, NEAR);
            const float px = fmaf(dx, t, ox);
            const float py = fmaf(dy, t, oy);
            const float pz = fmaf(dz, t, oz);
            const bool inb = (px >= ax0) & (px <= ax1) &
                             (py >= ay0) & (py <= ay1) &
                             (pz >= az0) & (pz <= az1);

            const float x = sf[s] + DENSITY_SHIFT;
            float sp = (x > 20.0f) ? x : __logf(1.0f + __expf(x));
            const float sigma = inb ? sp : 0.0f;

            const float e = __expf(-sigma * dist);
            const float alpha = 1.0f - e;
            const float f = e + 1e-10f;

            float incl = f;
            #pragma unroll
            for (int off = 1; off < 32; off <<= 1) {
                const float v = __shfl_up_sync(0xffffffffu, incl, off);
                if (lane >= off) incl *= v;
            }
            float excl = __shfl_up_sync(0xffffffffu, incl, 1);
            if (lane == 0) excl = 1.0f;

            const float w = alpha * runT * excl;

            racc += w * rg[s * 3 + 0];
            gacc += w * rg[s * 3 + 1];
            bacc += w * rg[s * 3 + 2];
            dacc += w * t;

            runT *= __shfl_sync(0xffffffffu, incl, 31);
        }

        #pragma unroll
        for (int off = 16; off; off >>= 1) {
            racc += __shfl_down_sync(0xffffffffu, racc, off);
            gacc += __shfl_down_sync(0xffffffffu, gacc, off);
            bacc += __shfl_down_sync(0xffffffffu, bacc, off);
            dacc += __shfl_down_sync(0xffffffffu, dacc, off);
        }

        if (lane == 0) {
            out[r * 3 + 0] = racc;
            out[r * 3 + 1] = gacc;
            out[r * 3 + 2] = bacc;
            out[3 * N + r] = dacc;
            out[4 * N + r] = runT;
        }
    }

    // Self-clean: last block resets counters for the next replay.
    __syncthreads();
    if (threadIdx.x == 0) {
        __threadfence();
        const int done = atomicAdd(&g_done, 1);
        if (done == gridDim.x - 1) {
            g_cnt  = 0;
            g_done = 0;
            __threadfence();
        }
    }
}

extern "C" void kernel_launch(void* const* d_in, const int* in_sizes, int n_in,
                              void* d_out, int out_size) {
    const float* rays_o     = (const float*)d_in[0];
    const float* rays_d     = (const float*)d_in[1];
    const float* sigma_feat = (const float*)d_in[2];
    const float* rgb        = (const float*)d_in[3];
    const float* aabb       = (const float*)d_in[4];
    float* out = (float*)d_out;

    const int N = in_sizes[0] / 3;

    phaseA_kernel<<<(N + 127) / 128, 128>>>(rays_o, rays_d, aabb, out, N);
    phaseB_kernel<<<PHASEB_BLOCKS, 256>>>(sigma_feat, rgb, aabb, out, N);
}